// round 17
// baseline (speedup 1.0000x reference)
#include <cuda_runtime.h>

#define NATOMS  1024
#define NBATCH  32
#define NTILE   8
#define TILE    128
#define QUADS   32            // quads of 4 j-atoms per tile
#define NPB     36            // tile-pairs per batch: 8 diag + 28 off-diag
#define THREADS 128           // one i-atom per thread, 4 warps per block
// grid = NBATCH * NPB = 1152 blocks of 128 threads

typedef unsigned long long ull;

__device__ __forceinline__ ull f2pack(float lo, float hi) {
    ull r;
    asm("mov.b64 %0, {%1, %2};" : "=l"(r)
        : "r"(__float_as_uint(lo)), "r"(__float_as_uint(hi)));
    return r;
}
__device__ __forceinline__ void f2unpack(ull v, float& lo, float& hi) {
    unsigned a, b;
    asm("mov.b64 {%0, %1}, %2;" : "=r"(a), "=r"(b) : "l"(v));
    lo = __uint_as_float(a);
    hi = __uint_as_float(b);
}
__device__ __forceinline__ ull f2add(ull a, ull b) {
    ull r; asm("add.rn.f32x2 %0, %1, %2;" : "=l"(r) : "l"(a), "l"(b)); return r;
}
__device__ __forceinline__ ull f2mul(ull a, ull b) {
    ull r; asm("mul.rn.f32x2 %0, %1, %2;" : "=l"(r) : "l"(a), "l"(b)); return r;
}
__device__ __forceinline__ ull f2fma(ull a, ull b, ull c) {
    ull r; asm("fma.rn.f32x2 %0, %1, %2, %3;" : "=l"(r) : "l"(a), "l"(b), "l"(c)); return r;
}

__global__ void lj_zero_out(float* __restrict__ out, int n) {
    int idx = blockIdx.x * blockDim.x + threadIdx.x;
    for (; idx < n; idx += gridDim.x * blockDim.x) out[idx] = 0.0f;
}

// Minimal LJ core: a = 1/r^2; u = a^3 - 1; ae += u^2 (= e_term + 1, count fixed
// in epilogue; self-pair contributes exactly +1); force coef c = a^4*u (self: 0).
__device__ __forceinline__ ull lj_core(
    ull xi2, ull yi2, ull zi2, ull nx2, ull ny2, ull nz2,
    int m, int m0, int m1, bool self_mask, ull MINUS1,
    ull& dx2o, ull& dy2o, ull& dz2o,
    ull& fx2, ull& fy2, ull& fz2, ull& ae)
{
    ull dx2 = f2add(xi2, nx2);
    ull dy2 = f2add(yi2, ny2);
    ull dz2 = f2add(zi2, nz2);
    ull sq2 = f2mul(dx2, dx2);
    sq2 = f2fma(dy2, dy2, sq2);
    sq2 = f2fma(dz2, dz2, sq2);
    float s0, s1;
    f2unpack(sq2, s0, s1);
    if (self_mask) {                    // self-pair -> rcp underflows to 0
        s0 = (m == m0) ? 3.0e38f : s0;
        s1 = (m == m1) ? 3.0e38f : s1;
    }
    float r0 = __fdividef(1.0f, s0);    // MUFU.RCP
    float r1 = __fdividef(1.0f, s1);
    ull a  = f2pack(r0, r1);
    ull a2 = f2mul(a, a);
    ull a3 = f2mul(a2, a);
    ull a4 = f2mul(a2, a2);
    ull um = f2add(a3, MINUS1);         // r^-6 - 1   (self: -1)
    ae = f2fma(um, um, ae);             // += e_term + 1  (self: +1)
    ull c2 = f2mul(a4, um);             // (r^-12 - r^-6)/r^2  (self: 0)
    fx2 = f2fma(c2, dx2, fx2);
    fy2 = f2fma(c2, dy2, fy2);
    fz2 = f2fma(c2, dz2, fz2);
    dx2o = dx2; dy2o = dy2; dz2o = dz2;
    return c2;
}

__global__ __launch_bounds__(THREADS, 8) void lj_kernel(const float* __restrict__ pos,
                                                        float* __restrict__ out) {
    // j-tile in quads: quad q holds atoms 4q..4q+3 (negated)
    __shared__ ulonglong2 sxq[QUADS];      // {x01, x23}
    __shared__ ulonglong2 syq[QUADS];      // {y01, y23}
    __shared__ ulonglong2 szq[QUADS];      // {z01, z23}
    __shared__ ulonglong2 gx[4][QUADS];    // per-warp j-force accumulators
    __shared__ ulonglong2 gy[4][QUADS];
    __shared__ ulonglong2 gz[4][QUADS];
    __shared__ float      wred[4 * 3];
    __shared__ float      ered[4];
    __shared__ float      smean[3];

    const int bi  = blockIdx.x;
    const int b   = bi / NPB;
    int rem = bi - b * NPB;                // tile-pair rank 0..35
    int ta = 0;
    while (rem >= NTILE - ta) { rem -= NTILE - ta; ta++; }
    const int tb = ta + rem;               // ta <= tb
    const bool diag = (ta == tb);

    const int tid  = threadIdx.x;
    const int lane = tid & 31;
    const int warp = tid >> 5;

    const float* __restrict__ p = pos + (size_t)b * NATOMS * 3;

    // one owned i-atom
    const int i0 = ta * TILE + tid;
    const float xa = p[3 * i0 + 0], ya = p[3 * i0 + 1], za = p[3 * i0 + 2];

    // stage quads (threads 0..31)
    if (tid < QUADS) {
        const int j0 = tb * TILE + 4 * tid;
        float v0x = p[3*j0+0], v0y = p[3*j0+1],  v0z = p[3*j0+2];
        float v1x = p[3*j0+3], v1y = p[3*j0+4],  v1z = p[3*j0+5];
        float v2x = p[3*j0+6], v2y = p[3*j0+7],  v2z = p[3*j0+8];
        float v3x = p[3*j0+9], v3y = p[3*j0+10], v3z = p[3*j0+11];
        ulonglong2 X, Y, Z;
        X.x = f2pack(-v0x, -v1x); X.y = f2pack(-v2x, -v3x);
        Y.x = f2pack(-v0y, -v1y); Y.y = f2pack(-v2y, -v3y);
        Z.x = f2pack(-v0z, -v1z); Z.y = f2pack(-v2z, -v3z);
        sxq[tid] = X; syq[tid] = Y; szq[tid] = Z;
    }
    // zero accumulators: 4 warps x 32 quads x 3 comps = 384 ulonglong2? no:
    // gx[4][32] = 128 ulonglong2 = 256 ull per comp; 128 threads x 2 each.
    #pragma unroll
    for (int k = 0; k < 2; k++) {
        ((ull*)gx)[k * THREADS + tid] = 0;
        ((ull*)gy)[k * THREADS + tid] = 0;
        ((ull*)gz)[k * THREADS + tid] = 0;
    }

    // diag blocks compute batch mean (for oscillator); off-diag skip
    if (diag) {
        float mx = 0.0f, my = 0.0f, mz = 0.0f;
        for (int a = tid; a < NATOMS; a += THREADS) {
            mx += p[3 * a + 0];
            my += p[3 * a + 1];
            mz += p[3 * a + 2];
        }
        #pragma unroll
        for (int o = 16; o > 0; o >>= 1) {
            mx += __shfl_xor_sync(0xFFFFFFFFu, mx, o);
            my += __shfl_xor_sync(0xFFFFFFFFu, my, o);
            mz += __shfl_xor_sync(0xFFFFFFFFu, mz, o);
        }
        if (lane == 0) {
            wred[warp * 3 + 0] = mx;
            wred[warp * 3 + 1] = my;
            wred[warp * 3 + 2] = mz;
        }
    }
    __syncthreads();
    if (diag && tid == 0) {
        const float inv_n = 1.0f / (float)NATOMS;
        smean[0] = (wred[0] + wred[3] + wred[6] + wred[9])  * inv_n;
        smean[1] = (wred[1] + wred[4] + wred[7] + wred[10]) * inv_n;
        smean[2] = (wred[2] + wred[5] + wred[8] + wred[11]) * inv_n;
    }
    if (diag) __syncthreads();

    const ull xa2 = f2pack(xa, xa), ya2 = f2pack(ya, ya), za2 = f2pack(za, za);
    const ull MINUS1 = f2pack(-1.0f, -1.0f);

    ull fxa = 0, fya = 0, fza = 0, aea = 0;

    if (diag) {
        // self-tile: atom index in tile = tid = 4*qa + 2*sub + slot.
        const int qa   = tid >> 2;
        const int sub  = (tid >> 1) & 1;
        const int slot = tid & 1;
        const int a00 = (sub == 0 && slot == 0) ? qa : -1;
        const int a01 = (sub == 0 && slot == 1) ? qa : -1;
        const int a10 = (sub == 1 && slot == 0) ? qa : -1;
        const int a11 = (sub == 1 && slot == 1) ? qa : -1;
        ull d0, d1, d2;
        #pragma unroll 4
        for (int t = 0; t < QUADS; t++) {
            ulonglong2 X = sxq[t], Y = syq[t], Z = szq[t];   // broadcast
            lj_core(xa2, ya2, za2, X.x, Y.x, Z.x, t, a00, a01, true, MINUS1,
                    d0, d1, d2, fxa, fya, fza, aea);
            lj_core(xa2, ya2, za2, X.y, Y.y, Z.y, t, a10, a11, true, MINUS1,
                    d0, d1, d2, fxa, fya, fza, aea);
        }
    } else {
        // cross-tile: lane rotation over quads; 128-bit j-RMW per component.
        ulonglong2* __restrict__ GX = gx[warp];
        ulonglong2* __restrict__ GY = gy[warp];
        ulonglong2* __restrict__ GZ = gz[warp];
        ull dax0, day0, daz0, dax1, day1, daz1;
        #pragma unroll 4
        for (int t = 0; t < QUADS; t++) {
            const int q = (t + lane) & (QUADS - 1);   // lanes on distinct quads
            ulonglong2 X = sxq[q], Y = syq[q], Z = szq[q];
            ull ca0 = lj_core(xa2, ya2, za2, X.x, Y.x, Z.x, 0, -1, -1, false, MINUS1,
                              dax0, day0, daz0, fxa, fya, fza, aea);
            ull ca1 = lj_core(xa2, ya2, za2, X.y, Y.y, Z.y, 0, -1, -1, false, MINUS1,
                              dax1, day1, daz1, fxa, fya, fza, aea);
            ulonglong2 vx = GX[q];
            vx.x = f2fma(ca0, dax0, vx.x);
            vx.y = f2fma(ca1, dax1, vx.y);
            GX[q] = vx;
            ulonglong2 vy = GY[q];
            vy.x = f2fma(ca0, day0, vy.x);
            vy.y = f2fma(ca1, day1, vy.y);
            GY[q] = vy;
            ulonglong2 vz = GZ[q];
            vz.x = f2fma(ca0, daz0, vz.x);
            vz.y = f2fma(ca1, daz1, vz.y);
            GZ[q] = vz;
        }
    }

    // energy: each core-lane added e_term + 1; 128 terms per thread
    const float ew = diag ? 0.5f : 1.0f;
    float e;
    {
        float l0, h0;
        f2unpack(aea, l0, h0);
        e = ew * ((l0 + h0) - 128.0f);
    }

    float fax, fay, faz;
    {
        float lo, hi;
        f2unpack(fxa, lo, hi); fax = 12.0f * (lo + hi);
        f2unpack(fya, lo, hi); fay = 12.0f * (lo + hi);
        f2unpack(fza, lo, hi); faz = 12.0f * (lo + hi);
    }

    if (diag) {
        // oscillator: each i belongs to exactly one diag block
        float xc = xa - smean[0], yc = ya - smean[1], zc = za - smean[2];
        e  += 0.125f * fmaf(xc, xc, fmaf(yc, yc, zc * zc));
        fax -= 0.25f * xc; fay -= 0.25f * yc; faz -= 0.25f * zc;
    }

    // i-side forces (output zero-initialized by lj_zero_out)
    float* __restrict__ fA = out + NBATCH + (size_t)(b * NATOMS + i0) * 3;
    atomicAdd(fA + 0, fax);
    atomicAdd(fA + 1, fay);
    atomicAdd(fA + 2, faz);

    __syncthreads();

    // j-side forces (off-diag only): reduce 4 warp copies per quad, negate, scale
    if (!diag && tid < QUADS) {
        ulonglong2 v0 = gx[0][tid], v1 = gx[1][tid], v2 = gx[2][tid], v3 = gx[3][tid];
        ull sx01 = f2add(f2add(v0.x, v1.x), f2add(v2.x, v3.x));
        ull sx23 = f2add(f2add(v0.y, v1.y), f2add(v2.y, v3.y));
        v0 = gy[0][tid]; v1 = gy[1][tid]; v2 = gy[2][tid]; v3 = gy[3][tid];
        ull sy01 = f2add(f2add(v0.x, v1.x), f2add(v2.x, v3.x));
        ull sy23 = f2add(f2add(v0.y, v1.y), f2add(v2.y, v3.y));
        v0 = gz[0][tid]; v1 = gz[1][tid]; v2 = gz[2][tid]; v3 = gz[3][tid];
        ull sz01 = f2add(f2add(v0.x, v1.x), f2add(v2.x, v3.x));
        ull sz23 = f2add(f2add(v0.y, v1.y), f2add(v2.y, v3.y));
        float x0, x1, x2, x3, y0, y1, y2, y3, z0, z1, z2, z3;
        f2unpack(sx01, x0, x1); f2unpack(sx23, x2, x3);
        f2unpack(sy01, y0, y1); f2unpack(sy23, y2, y3);
        f2unpack(sz01, z0, z1); f2unpack(sz23, z2, z3);
        const int j0 = tb * TILE + 4 * tid;
        float* __restrict__ fj = out + NBATCH + (size_t)(b * NATOMS + j0) * 3;
        atomicAdd(fj + 0,  -12.0f * x0);
        atomicAdd(fj + 1,  -12.0f * y0);
        atomicAdd(fj + 2,  -12.0f * z0);
        atomicAdd(fj + 3,  -12.0f * x1);
        atomicAdd(fj + 4,  -12.0f * y1);
        atomicAdd(fj + 5,  -12.0f * z1);
        atomicAdd(fj + 6,  -12.0f * x2);
        atomicAdd(fj + 7,  -12.0f * y2);
        atomicAdd(fj + 8,  -12.0f * z2);
        atomicAdd(fj + 9,  -12.0f * x3);
        atomicAdd(fj + 10, -12.0f * y3);
        atomicAdd(fj + 11, -12.0f * z3);
    }

    // energy: warp shuffles -> shared -> one atomicAdd per block
    #pragma unroll
    for (int o = 16; o > 0; o >>= 1)
        e += __shfl_xor_sync(0xFFFFFFFFu, e, o);
    if (lane == 0) ered[warp] = e;
    __syncthreads();
    if (tid == 0) atomicAdd(out + b, ered[0] + ered[1] + ered[2] + ered[3]);
}

extern "C" void kernel_launch(void* const* d_in, const int* in_sizes, int n_in,
                              void* d_out, int out_size) {
    const float* pos = (const float*)d_in[0];
    float* out = (float*)d_out;
    lj_zero_out<<<148, 256>>>(out, out_size);
    lj_kernel<<<NBATCH * NPB, THREADS>>>(pos, out);
}